// round 13
// baseline (speedup 1.0000x reference)
#include <cuda_runtime.h>
#include <cstdint>
#include <cmath>

#define TOKENS   16384
#define DMODEL   4096
#define NEXP     64
#define TOPK     8

#define TILE_T   128
#define KCH      32
#define NSTAGE   4
#define NITER    (DMODEL / KCH)

#define XS_STRIDE 36
#define WS_STRIDE 36
#define STAGE_FLOATS (TILE_T * XS_STRIDE + NEXP * WS_STRIDE)
#define SMEM_BYTES (NSTAGE * STAGE_FLOATS * 4)

// exp flush/clamp boundary ~ ln(2^-126)
#define T_F (-87.33654022f)
#define FLT_MIN_NORM 1.1754943508222875e-38

#define FIX_BLOCKS 2048
#define TOK_PER_FIXBLK (TOKENS / FIX_BLOCKS)   // 8

// deterministic per-token ambiguity flags (rewritten every call; no reset needed)
__device__ int g_flag[TOKENS];

__device__ __forceinline__ void cp_async16(void* smem_dst, const void* gmem_src) {
    uint32_t dst = (uint32_t)__cvta_generic_to_shared(smem_dst);
    asm volatile("cp.async.cg.shared.global [%0], [%1], 16;\n" :: "r"(dst), "l"(gmem_src));
}
__device__ __forceinline__ void cp_async_commit() {
    asm volatile("cp.async.commit_group;\n");
}
template <int N>
__device__ __forceinline__ void cp_async_wait() {
    asm volatile("cp.async.wait_group %0;\n" :: "n"(N));
}
__device__ __forceinline__ void fma2(unsigned long long& d,
                                     unsigned long long a,
                                     unsigned long long b) {
    asm("fma.rn.f32x2 %0, %1, %2, %0;" : "+l"(d) : "l"(a), "l"(b));
}

// ---- EXACT R11 passing epilogue (fp64 exp) — used ONLY in the fixup ----
__device__ __forceinline__ void epilogue_topk_fp64(const float* row, float* ow, float* oi)
{
    float m = row[0];
#pragma unroll 8
    for (int e = 1; e < NEXP; e++) m = fmaxf(m, row[e]);

    float sum = 0.0f;
    for (int e = 0; e < NEXP; e++) {
        float d = row[e] - m;
        if (d >= T_F) sum += __expf(d);
    }
    const double sumd = (double)sum;

    int keys[TOPK];
    int idxs[TOPK];
#pragma unroll
    for (int j = 0; j < TOPK; j++) { keys[j] = -1; idxs[j] = 0; }

    double qc = exp((double)T_F) / sumd;
    const int key_clamp = (qc < FLT_MIN_NORM) ? 0 : __float_as_int((float)qc);

    for (int e = 0; e < NEXP; e++) {
        float d = row[e] - m;
        int key;
        if (d < T_F) {
            key = key_clamp;
        } else {
            double q = exp((double)d) / sumd;
            key = (q < FLT_MIN_NORM) ? 0 : __float_as_int((float)q);
        }
        if (key > keys[TOPK - 1]) {
            keys[TOPK - 1] = key;
            idxs[TOPK - 1] = e;
#pragma unroll
            for (int q2 = TOPK - 1; q2 > 0; q2--) {
                if (keys[q2] > keys[q2 - 1]) {
                    int tk = keys[q2]; keys[q2] = keys[q2 - 1]; keys[q2 - 1] = tk;
                    int ti = idxs[q2]; idxs[q2] = idxs[q2 - 1]; idxs[q2 - 1] = ti;
                }
            }
        }
    }
#pragma unroll
    for (int j = 0; j < TOPK; j++) {
        ow[j] = __int_as_float(keys[j] < 0 ? 0 : keys[j]);
        oi[j] = (float)idxs[j];
    }
}

// ---------------- kernel 1: fast fp32 GEMM + fp32 epilogue + flagging ----------------
__global__ void __launch_bounds__(256, 1)
router_kernel(const float* __restrict__ x, const float* __restrict__ w,
              float* __restrict__ out_w, float* __restrict__ out_i)
{
    extern __shared__ float smem[];
    const int tid = threadIdx.x;
    const int tx  = tid & 15;
    const int ty  = tid >> 4;
    const int t_block = blockIdx.x * TILE_T;

    unsigned long long acc2[8][4];
#pragma unroll
    for (int i = 0; i < 8; i++)
#pragma unroll
        for (int j = 0; j < 4; j++) acc2[i][j] = 0ULL;

    auto issue_stage = [&](int stage, int it) {
        float* xs = smem + stage * STAGE_FLOATS;
        float* ws = xs + TILE_T * XS_STRIDE;
        const int kc = it * KCH;
#pragma unroll
        for (int q = 0; q < 4; q++) {
            int seg = tid + 256 * q;
            int row = seg >> 3;
            int c   = (seg & 7) * 4;
            cp_async16(&xs[row * XS_STRIDE + c],
                       &x[(size_t)(t_block + row) * DMODEL + kc + c]);
        }
#pragma unroll
        for (int q = 0; q < 2; q++) {
            int seg = tid + 256 * q;
            int row = seg >> 3;
            int c   = (seg & 7) * 4;
            cp_async16(&ws[row * WS_STRIDE + c],
                       &w[(size_t)row * DMODEL + kc + c]);
        }
        cp_async_commit();
    };

    for (int s = 0; s < NSTAGE - 1; s++) issue_stage(s, s);

    for (int it = 0; it < NITER; it++) {
        cp_async_wait<NSTAGE - 2>();
        __syncthreads();

        const float* xs = smem + (it & (NSTAGE - 1)) * STAGE_FLOATS;
        const float* ws = xs + TILE_T * XS_STRIDE;

#pragma unroll
        for (int k4 = 0; k4 < KCH / 4; k4++) {
            ulonglong2 wf2[4];
#pragma unroll
            for (int j = 0; j < 4; j++)
                wf2[j] = *(const ulonglong2*)&ws[(tx + 16 * j) * WS_STRIDE + k4 * 4];
#pragma unroll
            for (int i = 0; i < 8; i++) {
                ulonglong2 xf2 = *(const ulonglong2*)&xs[(ty + 16 * i) * XS_STRIDE + k4 * 4];
#pragma unroll
                for (int j = 0; j < 4; j++) {
                    fma2(acc2[i][j], xf2.x, wf2[j].x);
                    fma2(acc2[i][j], xf2.y, wf2[j].y);
                }
            }
        }

        int nxt = it + NSTAGE - 1;
        if (nxt < NITER) issue_stage(nxt & (NSTAGE - 1), nxt);
        else             cp_async_commit();
    }

    __syncthreads();
    float* lsm = smem;   // [128][65]
#pragma unroll
    for (int i = 0; i < 8; i++)
#pragma unroll
        for (int j = 0; j < 4; j++) {
            float2 p = *(float2*)&acc2[i][j];
            lsm[(ty + 16 * i) * 65 + (tx + 16 * j)] = p.x + p.y;
        }
    __syncthreads();

    if (tid < TILE_T) {
        const float* row = lsm + tid * 65;

        float m = row[0];
#pragma unroll 8
        for (int e = 1; e < NEXP; e++) m = fmaxf(m, row[e]);

        float sum = 0.0f;
        for (int e = 0; e < NEXP; e++) {
            float d = row[e] - m;
            if (d >= T_F) sum += __expf(d);
        }
        float rinv = 1.0f / sum;
        float bnd  = T_F + __logf(sum);   // effective tie boundary after division flush

        // ---- ambiguity flags (identical windows to passing R11 config) ----
        float dt[9];
#pragma unroll
        for (int q = 0; q < 9; q++) dt[q] = -3.0e38f;
        bool flag = false;
        for (int e = 0; e < NEXP; e++) {
            float d = row[e] - m;
            if (fabsf(d - T_F) < 0.05f || fabsf(d - bnd) < 0.05f) flag = true;
            if (d > dt[8]) {
                dt[8] = d;
#pragma unroll
                for (int q = 8; q > 0; q--)
                    if (dt[q] > dt[q - 1]) { float t = dt[q]; dt[q] = dt[q - 1]; dt[q - 1] = t; }
            }
        }
#pragma unroll
        for (int q = 0; q < 8; q++)
            if (dt[q] - dt[q + 1] < 0.003f && dt[q + 1] > T_F - 0.05f) flag = true;

        int gtok = t_block + tid;
        g_flag[gtok] = flag ? 1 : 0;

        // ---- FAST fp32 epilogue (flagged tokens get overwritten by fp64 fixup;
        //      unflagged tokens: margins >= 0.05/0.003 >> __expf error 2.4e-7,
        //      so decisions identical to the fp64 version) ----
        int keys[TOPK];
        int idxs[TOPK];
#pragma unroll
        for (int j = 0; j < TOPK; j++) { keys[j] = -1; idxs[j] = 0; }

        float qc = __expf(T_F) * rinv;
        const int key_clamp = (qc < FLT_MIN_NORM) ? 0 : __float_as_int(qc);

        for (int e = 0; e < NEXP; e++) {
            float d = row[e] - m;
            int key;
            if (d < T_F) {
                key = key_clamp;
            } else {
                float qf = __expf(d) * rinv;
                key = (qf < FLT_MIN_NORM) ? 0 : __float_as_int(qf);
            }
            if (key > keys[TOPK - 1]) {
                keys[TOPK - 1] = key;
                idxs[TOPK - 1] = e;
#pragma unroll
                for (int q2 = TOPK - 1; q2 > 0; q2--) {
                    if (keys[q2] > keys[q2 - 1]) {
                        int tk = keys[q2]; keys[q2] = keys[q2 - 1]; keys[q2 - 1] = tk;
                        int ti = idxs[q2]; idxs[q2] = idxs[q2 - 1]; idxs[q2 - 1] = ti;
                    }
                }
            }
        }

#pragma unroll
        for (int j = 0; j < TOPK; j++) {
            out_w[(size_t)gtok * TOPK + j] = __int_as_float(keys[j] < 0 ? 0 : keys[j]);
            out_i[(size_t)gtok * TOPK + j] = (float)idxs[j];
        }
    }
}

// ---------------- kernel 2: coalesced fp64 re-resolution of flagged tokens ----------------
__global__ void __launch_bounds__(256, 1)
router_fixup(const float* __restrict__ x, const float* __restrict__ w,
             float* __restrict__ out_w, float* __restrict__ out_i)
{
    __shared__ float lg[NEXP];

    const int tid  = threadIdx.x;
    const int wid  = tid >> 5;
    const int lane = tid & 31;
    const int tok0 = blockIdx.x * TOK_PER_FIXBLK;

    for (int t = 0; t < TOK_PER_FIXBLK; t++) {
        int tok = tok0 + t;
        if (g_flag[tok] == 0) continue;      // uniform read -> uniform branch

        const float* xr = x + (size_t)tok * DMODEL;
        const float* w0 = w + (size_t)(wid * 8) * DMODEL;

        double acc[8];
#pragma unroll
        for (int e8 = 0; e8 < 8; e8++) acc[e8] = 0.0;

        for (int k = lane; k < DMODEL; k += 32) {
            double xv = (double)xr[k];
#pragma unroll
            for (int e8 = 0; e8 < 8; e8++)
                acc[e8] = fma(xv, (double)w0[e8 * DMODEL + k], acc[e8]);
        }

#pragma unroll
        for (int e8 = 0; e8 < 8; e8++) {
            double s = acc[e8];
#pragma unroll
            for (int o = 16; o; o >>= 1) s += __shfl_down_sync(0xFFFFFFFFu, s, o);
            if (lane == 0) lg[wid * 8 + e8] = (float)s;
        }
        __syncthreads();

        if (tid == 0)
            epilogue_topk_fp64(lg, out_w + (size_t)tok * TOPK, out_i + (size_t)tok * TOPK);
        __syncthreads();
    }
}

extern "C" void kernel_launch(void* const* d_in, const int* in_sizes, int n_in,
                              void* d_out, int out_size)
{
    const float* x = (const float*)d_in[0];
    const float* w = (const float*)d_in[1];

    float* out_w = (float*)d_out;
    float* out_i = (float*)d_out + (size_t)TOKENS * TOPK;

    cudaFuncSetAttribute(router_kernel,
                         cudaFuncAttributeMaxDynamicSharedMemorySize, SMEM_BYTES);

    router_kernel<<<TOKENS / TILE_T, 256, SMEM_BYTES>>>(x, w, out_w, out_i);
    router_fixup<<<FIX_BLOCKS, 256>>>(x, w, out_w, out_i);
}

// round 14
// speedup vs baseline: 2.9198x; 2.9198x over previous
#include <cuda_runtime.h>
#include <cstdint>
#include <cmath>

#define TOKENS   16384
#define DMODEL   4096
#define NEXP     64
#define TOPK     8

#define TILE_T   128
#define KCH      32
#define NSTAGE   4
#define NITER    (DMODEL / KCH)

#define XS_STRIDE 36
#define WS_STRIDE 36
#define STAGE_FLOATS (TILE_T * XS_STRIDE + NEXP * WS_STRIDE)
#define SMEM_BYTES (NSTAGE * STAGE_FLOATS * 4)

// exp flush/clamp boundary ~ ln(2^-126)
#define T_F (-87.33654022f)
#define FLT_MIN_NORM 1.1754943508222875e-38

// flag windows: my fp32-GEMM logit noise sigma ~= 2.4e-4; 0.004 ~= 16 sigma
#define WIN_CLAMP 0.004f
#define WIN_GAP   0.003f

#define FIX_BLOCKS 256

__device__ int g_count;
__device__ int g_list[TOKENS];

__device__ __forceinline__ void cp_async16(void* smem_dst, const void* gmem_src) {
    uint32_t dst = (uint32_t)__cvta_generic_to_shared(smem_dst);
    asm volatile("cp.async.cg.shared.global [%0], [%1], 16;\n" :: "r"(dst), "l"(gmem_src));
}
__device__ __forceinline__ void cp_async_commit() {
    asm volatile("cp.async.commit_group;\n");
}
template <int N>
__device__ __forceinline__ void cp_async_wait() {
    asm volatile("cp.async.wait_group %0;\n" :: "n"(N));
}
__device__ __forceinline__ void fma2(unsigned long long& d,
                                     unsigned long long a,
                                     unsigned long long b) {
    asm("fma.rn.f32x2 %0, %1, %2, %0;" : "+l"(d) : "l"(a), "l"(b));
}

__global__ void reset_kernel() { if (threadIdx.x == 0) g_count = 0; }

// ---------------- kernel 1: fast fp32 GEMM + fp32 epilogue + flagging ----------------
__global__ void __launch_bounds__(256, 1)
router_kernel(const float* __restrict__ x, const float* __restrict__ w,
              float* __restrict__ out_w, float* __restrict__ out_i)
{
    extern __shared__ float smem[];
    const int tid = threadIdx.x;
    const int tx  = tid & 15;
    const int ty  = tid >> 4;
    const int t_block = blockIdx.x * TILE_T;

    unsigned long long acc2[8][4];
#pragma unroll
    for (int i = 0; i < 8; i++)
#pragma unroll
        for (int j = 0; j < 4; j++) acc2[i][j] = 0ULL;

    auto issue_stage = [&](int stage, int it) {
        float* xs = smem + stage * STAGE_FLOATS;
        float* ws = xs + TILE_T * XS_STRIDE;
        const int kc = it * KCH;
#pragma unroll
        for (int q = 0; q < 4; q++) {
            int seg = tid + 256 * q;
            int row = seg >> 3;
            int c   = (seg & 7) * 4;
            cp_async16(&xs[row * XS_STRIDE + c],
                       &x[(size_t)(t_block + row) * DMODEL + kc + c]);
        }
#pragma unroll
        for (int q = 0; q < 2; q++) {
            int seg = tid + 256 * q;
            int row = seg >> 3;
            int c   = (seg & 7) * 4;
            cp_async16(&ws[row * WS_STRIDE + c],
                       &w[(size_t)row * DMODEL + kc + c]);
        }
        cp_async_commit();
    };

    for (int s = 0; s < NSTAGE - 1; s++) issue_stage(s, s);

    for (int it = 0; it < NITER; it++) {
        cp_async_wait<NSTAGE - 2>();
        __syncthreads();

        const float* xs = smem + (it & (NSTAGE - 1)) * STAGE_FLOATS;
        const float* ws = xs + TILE_T * XS_STRIDE;

#pragma unroll
        for (int k4 = 0; k4 < KCH / 4; k4++) {
            ulonglong2 wf2[4];
#pragma unroll
            for (int j = 0; j < 4; j++)
                wf2[j] = *(const ulonglong2*)&ws[(tx + 16 * j) * WS_STRIDE + k4 * 4];
#pragma unroll
            for (int i = 0; i < 8; i++) {
                ulonglong2 xf2 = *(const ulonglong2*)&xs[(ty + 16 * i) * XS_STRIDE + k4 * 4];
#pragma unroll
                for (int j = 0; j < 4; j++) {
                    fma2(acc2[i][j], xf2.x, wf2[j].x);
                    fma2(acc2[i][j], xf2.y, wf2[j].y);
                }
            }
        }

        int nxt = it + NSTAGE - 1;
        if (nxt < NITER) issue_stage(nxt & (NSTAGE - 1), nxt);
        else             cp_async_commit();
    }

    __syncthreads();
    float* lsm = smem;   // [128][65]
#pragma unroll
    for (int i = 0; i < 8; i++)
#pragma unroll
        for (int j = 0; j < 4; j++) {
            float2 p = *(float2*)&acc2[i][j];
            lsm[(ty + 16 * i) * 65 + (tx + 16 * j)] = p.x + p.y;
        }
    __syncthreads();

    if (tid < TILE_T) {
        const float* row = lsm + tid * 65;

        float m = row[0];
#pragma unroll 8
        for (int e = 1; e < NEXP; e++) m = fmaxf(m, row[e]);

        float sum = 0.0f;
        for (int e = 0; e < NEXP; e++) {
            float d = row[e] - m;
            if (d >= T_F) sum += __expf(d);
        }
        float rinv = 1.0f / sum;
        float bnd  = T_F + __logf(sum);   // effective tie boundary after division flush

        // ---- ambiguity flags (tight windows; tokens outside provably decide
        //      identically in fp32 and fp64) ----
        float dt[9];
#pragma unroll
        for (int q = 0; q < 9; q++) dt[q] = -3.0e38f;
        bool flag = false;
        for (int e = 0; e < NEXP; e++) {
            float d = row[e] - m;
            if (fabsf(d - T_F) < WIN_CLAMP || fabsf(d - bnd) < WIN_CLAMP) flag = true;
            if (d > dt[8]) {
                dt[8] = d;
#pragma unroll
                for (int q = 8; q > 0; q--)
                    if (dt[q] > dt[q - 1]) { float t = dt[q]; dt[q] = dt[q - 1]; dt[q - 1] = t; }
            }
        }
#pragma unroll
        for (int q = 0; q < 8; q++)
            if (dt[q] - dt[q + 1] < WIN_GAP && dt[q + 1] > T_F - WIN_CLAMP) flag = true;

        int gtok = t_block + tid;
        if (flag) {
            int slot = atomicAdd(&g_count, 1);
            if (slot < TOKENS) g_list[slot] = gtok;
        }

        // ---- fast fp32 epilogue (flagged tokens overwritten by fp64 fixup) ----
        int keys[TOPK];
        int idxs[TOPK];
#pragma unroll
        for (int j = 0; j < TOPK; j++) { keys[j] = -1; idxs[j] = 0; }

        float qc = __expf(T_F) * rinv;
        const int key_clamp = (qc < FLT_MIN_NORM) ? 0 : __float_as_int(qc);

        for (int e = 0; e < NEXP; e++) {
            float d = row[e] - m;
            int key;
            if (d < T_F) {
                key = key_clamp;
            } else {
                float qf = __expf(d) * rinv;
                key = (qf < FLT_MIN_NORM) ? 0 : __float_as_int(qf);
            }
            if (key > keys[TOPK - 1]) {
                keys[TOPK - 1] = key;
                idxs[TOPK - 1] = e;
#pragma unroll
                for (int q2 = TOPK - 1; q2 > 0; q2--) {
                    if (keys[q2] > keys[q2 - 1]) {
                        int tk = keys[q2]; keys[q2] = keys[q2 - 1]; keys[q2 - 1] = tk;
                        int ti = idxs[q2]; idxs[q2] = idxs[q2 - 1]; idxs[q2 - 1] = ti;
                    }
                }
            }
        }

#pragma unroll
        for (int j = 0; j < TOPK; j++) {
            out_w[(size_t)gtok * TOPK + j] = __int_as_float(keys[j] < 0 ? 0 : keys[j]);
            out_i[(size_t)gtok * TOPK + j] = (float)idxs[j];
        }
    }
}

// ---------------- kernel 2: fp64 re-resolution, PARALLEL epilogue ----------------
// Per flagged token: warps compute fp64 logits coalesced (as R13), then 64
// threads compute one R11-exact key each (one exp(double) per thread instead
// of 64 serial on thread 0), thread 0 does integer-only top-8 insertion.
__global__ void __launch_bounds__(256, 1)
router_fixup(const float* __restrict__ x, const float* __restrict__ w,
             float* __restrict__ out_w, float* __restrict__ out_i)
{
    __shared__ float  lg[NEXP];
    __shared__ int    skey[NEXP];
    __shared__ float  s_m;
    __shared__ double s_sumd;

    const int tid  = threadIdx.x;
    const int wid  = tid >> 5;
    const int lane = tid & 31;

    int total = g_count;
    if (total > TOKENS) total = TOKENS;

    for (int li = blockIdx.x; li < total; li += FIX_BLOCKS) {
        int tok = g_list[li];
        const float* xr = x + (size_t)tok * DMODEL;
        const float* w0 = w + (size_t)(wid * 8) * DMODEL;

        double acc[8];
#pragma unroll
        for (int e8 = 0; e8 < 8; e8++) acc[e8] = 0.0;

        for (int k = lane; k < DMODEL; k += 32) {
            double xv = (double)xr[k];
#pragma unroll
            for (int e8 = 0; e8 < 8; e8++)
                acc[e8] = fma(xv, (double)w0[e8 * DMODEL + k], acc[e8]);
        }

#pragma unroll
        for (int e8 = 0; e8 < 8; e8++) {
            double s = acc[e8];
#pragma unroll
            for (int o = 16; o; o >>= 1) s += __shfl_down_sync(0xFFFFFFFFu, s, o);
            if (lane == 0) lg[wid * 8 + e8] = (float)s;
        }
        __syncthreads();

        // R11-exact m and sum (fp32, index order) on one thread — cheap (MUFU)
        if (tid == 0) {
            float m = lg[0];
#pragma unroll 8
            for (int e = 1; e < NEXP; e++) m = fmaxf(m, lg[e]);
            float sum = 0.0f;
            for (int e = 0; e < NEXP; e++) {
                float d = lg[e] - m;
                if (d >= T_F) sum += __expf(d);
            }
            s_m = m;
            s_sumd = (double)sum;
        }
        __syncthreads();

        // parallel keys: R11 formula verbatim, one expert per thread
        if (tid < NEXP) {
            float d = lg[tid] - s_m;
            double dd = (d < T_F) ? (double)T_F : (double)d;
            double q  = exp(dd) / s_sumd;
            skey[tid] = (q < FLT_MIN_NORM) ? 0 : __float_as_int((float)q);
        }
        __syncthreads();

        // integer-only insertion (same ascending-e order, strict '>')
        if (tid == 0) {
            int keys[TOPK];
            int idxs[TOPK];
#pragma unroll
            for (int j = 0; j < TOPK; j++) { keys[j] = -1; idxs[j] = 0; }

            for (int e = 0; e < NEXP; e++) {
                int key = skey[e];
                if (key > keys[TOPK - 1]) {
                    keys[TOPK - 1] = key;
                    idxs[TOPK - 1] = e;
#pragma unroll
                    for (int q2 = TOPK - 1; q2 > 0; q2--) {
                        if (keys[q2] > keys[q2 - 1]) {
                            int tk = keys[q2]; keys[q2] = keys[q2 - 1]; keys[q2 - 1] = tk;
                            int ti = idxs[q2]; idxs[q2] = idxs[q2 - 1]; idxs[q2 - 1] = ti;
                        }
                    }
                }
            }
#pragma unroll
            for (int j = 0; j < TOPK; j++) {
                out_w[(size_t)tok * TOPK + j] = __int_as_float(keys[j] < 0 ? 0 : keys[j]);
                out_i[(size_t)tok * TOPK + j] = (float)idxs[j];
            }
        }
        __syncthreads();
    }
}

extern "C" void kernel_launch(void* const* d_in, const int* in_sizes, int n_in,
                              void* d_out, int out_size)
{
    const float* x = (const float*)d_in[0];
    const float* w = (const float*)d_in[1];

    float* out_w = (float*)d_out;
    float* out_i = (float*)d_out + (size_t)TOKENS * TOPK;

    cudaFuncSetAttribute(router_kernel,
                         cudaFuncAttributeMaxDynamicSharedMemorySize, SMEM_BYTES);

    reset_kernel<<<1, 32>>>();
    router_kernel<<<TOKENS / TILE_T, 256, SMEM_BYTES>>>(x, w, out_w, out_i);
    router_fixup<<<FIX_BLOCKS, 256>>>(x, w, out_w, out_i);
}